// round 7
// baseline (speedup 1.0000x reference)
#include <cuda_runtime.h>
#include <math.h>

#define KT      100
#define VDIM    8192
#define TOPN    20
#define NWORDS  (VDIM / 32)    // 256 bitmask words
#define SLICES  8
#define NB      (KT * SLICES)  // 800 blocks for loss phases
#define CANDMAX 512

// ---------------- scratch (device globals; zero-initialized at load) --------
__device__ float    g_p[KT * TOPN];
__device__ int      g_idx[KT * TOPN];
__device__ float    g_rowmax[KT];
__device__ unsigned g_U1[NWORDS];          // v in >=1 topic's top-20
__device__ unsigned g_U2[NWORDS];          // v in >=2 topics' top-20
__device__ unsigned g_mn[KT], g_mx[KT];    // per-topic min/max of M (uint-ordered)
__device__ float    g_M[KT * VDIM];        // 3.2 MB staged M (L2-resident)
__device__ float    g_rowsum[NB];          // per-item sum of exp(beta-rowmax)
__device__ double   g_partial[NB * 2];     // per-item UNNORMALIZED (pos, neg)
__device__ unsigned g_flag[KT];            // per-topic "topk ready" flag
__device__ unsigned g_done;                // completion counter

// ===== kernel 1: fused per-topic topk (producer) + sparse p@W (all) =========
// 800 blocks x 256 threads, all co-resident (888 slots at 6 blocks/SM x 148).
// Block (k, sl==0) computes topic k's top-20 and raises g_flag[k]; blocks
// (k, sl!=0) poll the flag. Then every block accumulates its 1024-column
// slice of M = p @ W, stores it, and merges per-topic min/max atomically.
__global__ void __launch_bounds__(256, 6) lossA_kernel(
    const float* __restrict__ Wmat, const float* __restrict__ beta)
{
    __shared__ float    smax[256];
    __shared__ float    cval[CANDMAX];
    __shared__ int      cidx[CANDMAX];
    __shared__ int      ccnt;
    __shared__ float    sthr[2];            // [0]=tau, [1]=rowmax
    __shared__ float    topv_s[TOPN];
    __shared__ int      topi_s[TOPN];
    __shared__ float    sp[TOPN];
    __shared__ int      si[TOPN];
    __shared__ float    r1[8], r2[8];

    const int b    = blockIdx.x;
    const int k    = b >> 3;
    const int sl   = b & 7;
    const int tid  = threadIdx.x;
    const int warp = tid >> 5;
    const int lane = tid & 31;

    if (sl == 0) {
        // ---------------- producer: topic k's top-20 ------------------------
        if (tid == 0) ccnt = 0;
        const float4* b4 = (const float4*)(beta + (size_t)k * VDIM);

        // per-thread max over 8 float4s (32 elements)
        float tm = -INFINITY;
        #pragma unroll
        for (int i = 0; i < 8; ++i) {
            float4 t = __ldg(b4 + tid + i * 256);
            tm = fmaxf(tm, fmaxf(fmaxf(t.x, t.y), fmaxf(t.z, t.w)));
        }
        smax[tid] = tm;
        __syncthreads();

        // warp 0: tau = 20th largest of the 256 thread-maxima.
        // Bound: if tau > x20 then >=20 threads each hold an element > x20
        // -> >=20 elements > x20 -> contradiction. So {v >= tau} ⊇ top-20.
        if (warp == 0) {
            float v[8];
            #pragma unroll
            for (int i = 0; i < 8; ++i) v[i] = smax[lane + 32 * i];
            unsigned used = 0u;
            float tau = 0.f, rmax = 0.f;
            for (int r = 0; r < TOPN; ++r) {
                float lm = -INFINITY; int li = -1;
                #pragma unroll
                for (int i = 0; i < 8; ++i)
                    if (!((used >> i) & 1u) && v[i] > lm) { lm = v[i]; li = i; }
                float wm = lm;
                #pragma unroll
                for (int o = 16; o; o >>= 1) wm = fmaxf(wm, __shfl_xor_sync(0xFFFFFFFFu, wm, o));
                if (r == 0) rmax = wm;
                tau = wm;
                unsigned bm = __ballot_sync(0xFFFFFFFFu, lm == wm);
                if (lane == (int)(__ffs(bm) - 1)) used |= 1u << li;
            }
            if (lane == 0) { sthr[0] = tau; sthr[1] = rmax; }
        }
        __syncthreads();
        const float tau = sthr[0];

        // candidate collection (reload from L1; expected ~40-60 candidates)
        #pragma unroll
        for (int i = 0; i < 8; ++i) {
            float4 t = __ldg(b4 + tid + i * 256);
            const int c0 = 4 * (tid + i * 256);
            float cv[4] = {t.x, t.y, t.z, t.w};
            #pragma unroll
            for (int c = 0; c < 4; ++c) {
                if (cv[c] >= tau) {
                    int p = atomicAdd(&ccnt, 1);
                    if (p < CANDMAX) { cval[p] = cv[c]; cidx[p] = c0 + c; }
                }
            }
        }
        __syncthreads();

        // warp 0: exact top-20 by (val desc, idx asc), sort by idx, softmax p
        if (warp == 0) {
            const int cnt = min(ccnt, CANDMAX);
            for (int r = 0; r < TOPN; ++r) {
                float lm = -INFINITY; int li = 0x7fffffff; int ls = -1;
                for (int i = lane; i < cnt; i += 32) {
                    float x = cval[i]; int ix = cidx[i];
                    if (x > lm || (x == lm && ix < li)) { lm = x; li = ix; ls = i; }
                }
                #pragma unroll
                for (int o = 16; o; o >>= 1) {
                    float ov = __shfl_xor_sync(0xFFFFFFFFu, lm, o);
                    int   oi = __shfl_xor_sync(0xFFFFFFFFu, li, o);
                    int   os = __shfl_xor_sync(0xFFFFFFFFu, ls, o);
                    if (ov > lm || (ov == lm && oi < li)) { lm = ov; li = oi; ls = os; }
                }
                if (lane == 0) { topv_s[r] = lm; topi_s[r] = li; cval[ls] = -INFINITY; }
                __syncwarp();
            }

            // sort the 20 by index (rank = #smaller indices; a permutation)
            float myv = 0.f; int myi = 0x7fffffff;
            if (lane < TOPN) { myv = topv_s[lane]; myi = topi_s[lane]; }
            int rank = 0;
            #pragma unroll
            for (int j = 0; j < TOPN; ++j) rank += (topi_s[j] < myi);
            __syncwarp();
            if (lane < TOPN) { topv_s[rank] = myv; topi_s[rank] = myi; }
            __syncwarp();

            // masked softmax over the 20 (rest underflows to exact 0 in fp32)
            const float rmax = sthr[1];
            float e20 = (lane < TOPN) ? expf(topv_s[lane] - rmax) : 0.f;
            float ps = e20;
            #pragma unroll
            for (int o = 16; o; o >>= 1) ps += __shfl_xor_sync(0xFFFFFFFFu, ps, o);
            const float invp = 1.0f / ps;

            if (lane < TOPN) {
                const float pv = e20 * invp;
                const int   ix = topi_s[lane];
                sp[lane] = pv;  si[lane] = ix;
                g_p[k * TOPN + lane]   = pv;
                g_idx[k * TOPN + lane] = ix;
                unsigned w = (unsigned)ix >> 5, mb = 1u << (ix & 31);
                unsigned old = atomicOr(&g_U1[w], mb);
                if (old & mb) atomicOr(&g_U2[w], mb);
            }
            if (lane == 0) {
                g_rowmax[k] = rmax;
                g_mn[k] = 0x7F800000u;   // +inf (per-replay re-init)
                g_mx[k] = 0u;
            }
        }
        __syncthreads();
        if (tid == 0) {
            __threadfence();
            atomicExch(&g_flag[k], 1u);
        }
    } else {
        // ---------------- consumer: wait for topic k's topk -----------------
        if (tid == 0) {
            while (atomicAdd(&g_flag[k], 0u) == 0u) __nanosleep(64);
            __threadfence();
        }
        __syncthreads();
        if (tid < TOPN) {
            sp[tid] = __ldcg(&g_p[k * TOPN + tid]);
            si[tid] = __ldcg(&g_idx[k * TOPN + tid]);
        }
        __syncthreads();
    }

    // ---------------- common: sparse p@W slice, store M, merge min/max ------
    const int v0 = sl * 1024 + tid * 4;
    float ax = 0.f, ay = 0.f, az = 0.f, aw = 0.f;
    #pragma unroll
    for (int j = 0; j < TOPN; ++j) {
        const float pj = sp[j];
        float4 w = __ldg((const float4*)(Wmat + (size_t)si[j] * VDIM + v0));
        ax = fmaf(pj, w.x, ax); ay = fmaf(pj, w.y, ay);
        az = fmaf(pj, w.z, az); aw = fmaf(pj, w.w, aw);
    }
    *(float4*)(g_M + (size_t)k * VDIM + v0) = make_float4(ax, ay, az, aw);

    float mn = fminf(fminf(ax, ay), fminf(az, aw));
    float mx = fmaxf(fmaxf(ax, ay), fmaxf(az, aw));
    #pragma unroll
    for (int o = 16; o; o >>= 1) {
        mn = fminf(mn, __shfl_xor_sync(0xFFFFFFFFu, mn, o));
        mx = fmaxf(mx, __shfl_xor_sync(0xFFFFFFFFu, mx, o));
    }
    if (lane == 0) { r1[warp] = mn; r2[warp] = mx; }
    __syncthreads();
    if (warp == 0) {
        mn = r1[lane & 7]; mx = r2[lane & 7];
        #pragma unroll
        for (int o = 4; o; o >>= 1) {
            mn = fminf(mn, __shfl_xor_sync(0xFFFFFFFFu, mn, o));
            mx = fmaxf(mx, __shfl_xor_sync(0xFFFFFFFFu, mx, o));
        }
        if (lane == 0) {
            // M >= 0 everywhere, so uint ordering == float ordering
            atomicMin(&g_mn[k], __float_as_uint(mn));
            atomicMax(&g_mx[k], __float_as_uint(mx));
        }
    }
}

// ===== kernel 2: Wc, unnormalized loss, rowsum, fused final reduction =======
__global__ void __launch_bounds__(256) lossB_kernel(
    const float* __restrict__ beta, const int* __restrict__ epoch,
    float* __restrict__ out)
{
    __shared__ int    si[TOPN];
    __shared__ float  r1[8], r2[8], r3[8];
    __shared__ double d1[8], d2[8];
    __shared__ int    is_last;

    const int b    = blockIdx.x;
    const int k    = b >> 3;
    const int sl   = b & 7;
    const int tid  = threadIdx.x;
    const int warp = tid >> 5;
    const int lane = tid & 31;

    if (tid < TOPN) si[tid] = g_idx[k * TOPN + tid];
    __syncthreads();

    const int v0         = sl * 1024 + tid * 4;
    const unsigned word  = (unsigned)v0 >> 5;
    const int      shift = v0 & 31;

    unsigned ow = 0u;
    #pragma unroll
    for (int j = 0; j < TOPN; ++j)
        if (((unsigned)si[j] >> 5) == word) ow |= 1u << (si[j] & 31);

    const float mn   = __uint_as_float(g_mn[k]);
    const float mx   = __uint_as_float(g_mx[k]);
    const float invr = 1.0f / (mx - mn);
    const float rmax = g_rowmax[k];

    float4 m  = *(const float4*)(g_M + (size_t)k * VDIM + v0);
    float4 bt = __ldg((const float4*)(beta + (size_t)k * VDIM + v0));
    const unsigned u1 = g_U1[word], u2 = g_U2[word];

    float mv[4] = {m.x, m.y, m.z, m.w};
    float bv[4] = {bt.x, bt.y, bt.z, bt.w};
    float pos = 0.f, neg = 0.f, es = 0.f;
    #pragma unroll
    for (int c = 0; c < 4; ++c) {
        const float wc = 1.0f - (mv[c] - mn) * invr;
        const float e  = expf(bv[c] - rmax);       // unnormalized softmax numerator
        es += e;
        const float l  = 100.0f * e * e * wc;      // scaled by 1/S^2 at the end
        const unsigned mb = 1u << (shift + c);
        const bool md = (ow & mb) ? (u2 & mb) : (u1 & mb);
        if (md) pos += l; else neg += l;
    }
    #pragma unroll
    for (int o = 16; o; o >>= 1) {
        pos += __shfl_xor_sync(0xFFFFFFFFu, pos, o);
        neg += __shfl_xor_sync(0xFFFFFFFFu, neg, o);
        es  += __shfl_xor_sync(0xFFFFFFFFu, es, o);
    }
    if (lane == 0) { r1[warp] = pos; r2[warp] = neg; r3[warp] = es; }
    __syncthreads();
    if (warp == 0) {
        pos = r1[lane & 7]; neg = r2[lane & 7]; es = r3[lane & 7];
        #pragma unroll
        for (int o = 4; o; o >>= 1) {
            pos += __shfl_xor_sync(0xFFFFFFFFu, pos, o);
            neg += __shfl_xor_sync(0xFFFFFFFFu, neg, o);
            es  += __shfl_xor_sync(0xFFFFFFFFu, es, o);
        }
    }

    if (tid == 0) {
        g_partial[2 * b]     = (double)pos;
        g_partial[2 * b + 1] = (double)neg;
        g_rowsum[b]          = es;
        __threadfence();
        unsigned r = atomicAdd(&g_done, 1u);
        is_last = (r == NB - 1);
    }
    __syncthreads();

    if (is_last) {
        __threadfence();
        double P = 0.0, N = 0.0;
        for (int t = tid; t < KT; t += 256) {        // only tid<100 active
            double S = 0.0, p = 0.0, n = 0.0;
            #pragma unroll
            for (int s2 = 0; s2 < SLICES; ++s2) {
                S += (double)g_rowsum[t * SLICES + s2];
                p += g_partial[2 * (t * SLICES + s2)];
                n += g_partial[2 * (t * SLICES + s2) + 1];
            }
            const double inv = 1.0 / (S * S);
            P += p * inv; N += n * inv;
        }
        #pragma unroll
        for (int o = 16; o; o >>= 1) {
            P += __shfl_xor_sync(0xFFFFFFFFu, P, o);
            N += __shfl_xor_sync(0xFFFFFFFFu, N, o);
        }
        if (lane == 0) { d1[warp] = P; d2[warp] = N; }
        __syncthreads();
        if (warp == 0) {
            P = d1[lane & 7]; N = d2[lane & 7];
            #pragma unroll
            for (int o = 4; o; o >>= 1) {
                P += __shfl_xor_sync(0xFFFFFFFFu, P, o);
                N += __shfl_xor_sync(0xFFFFFFFFu, N, o);
            }
            if (lane == 0) {
                const int e = *epoch;                 // warmup = 100, delta = 1.0
                const float lam = (e < 100) ? (float)e : 100.0f;
                out[0] = lam * (float)((P * 0.7 + N * 0.3) * 2.0);
                g_done = 0;                           // reset for next replay
            }
        }
        g_U1[tid] = 0u;   // NWORDS == 256 == blockDim
        g_U2[tid] = 0u;
        if (tid < KT) g_flag[tid] = 0u;               // reset topk flags
    }
}

// ---------------- launch -----------------------------------------------------
extern "C" void kernel_launch(void* const* d_in, const int* in_sizes, int n_in,
                              void* d_out, int out_size) {
    const float* beta  = (const float*)d_in[0];
    const float* Wmat  = (const float*)d_in[1];
    const int*   epoch = (const int*)d_in[2];
    float* out = (float*)d_out;

    lossA_kernel<<<NB, 256>>>(Wmat, beta);
    lossB_kernel<<<NB, 256>>>(beta, epoch, out);
}

// round 10
// speedup vs baseline: 1.0791x; 1.0791x over previous
#include <cuda_runtime.h>
#include <math.h>

#define KT      100
#define VDIM    8192
#define TOPN    20
#define NWORDS  (VDIM / 32)    // 256 bitmask words
#define SLICES  8
#define NB      (KT * SLICES)  // 800 fused-loss blocks
#define CANDMAX 2048

// ---------------- scratch (device globals; zero-initialized at load) --------
__device__ float    g_p[KT * TOPN];
__device__ int      g_idx[KT * TOPN];
__device__ float    g_rowmax[KT];
__device__ unsigned g_U1[NWORDS];          // v in >=1 topic's top-20
__device__ unsigned g_U2[NWORDS];          // v in >=2 topics' top-20
__device__ unsigned g_mn[KT], g_mx[KT];    // per-topic min/max of M (uint-ordered)
__device__ unsigned g_tcnt[KT];            // per-topic stage-1 completion count
__device__ float    g_rowsum[NB];          // per-item sum of exp(beta-rowmax)
__device__ double   g_partial[NB * 2];     // per-item UNNORMALIZED (pos, neg)
__device__ unsigned g_done;                // completion counter

// ============ kernel 1: threshold-prune top-20 (1024 threads) ===============
__global__ void __launch_bounds__(1024) topk_kernel(const float* __restrict__ beta) {
    __shared__ float wmax[32];
    __shared__ float cval[CANDMAX];
    __shared__ int   cidx[CANDMAX];
    __shared__ int   ccnt;
    __shared__ float sthr[2];             // [0]=tau, [1]=rowmax
    __shared__ float topv_s[TOPN];
    __shared__ int   topi_s[TOPN];

    const int k    = blockIdx.x;
    const int tid  = threadIdx.x;
    const int warp = tid >> 5;
    const int lane = tid & 31;

    if (tid == 0) { g_mn[k] = 0x7F800000u; g_mx[k] = 0u; ccnt = 0; }

    // 2 coalesced float4 loads per thread
    const float4* b4 = (const float4*)(beta + (size_t)k * VDIM);
    float4 a = __ldg(b4 + tid);
    float4 b = __ldg(b4 + tid + 1024);
    float rv[8] = {a.x, a.y, a.z, a.w, b.x, b.y, b.z, b.w};
    // idx(e) = (e<4) ? 4*tid+e : 4096 + 4*tid + (e-4)

    // per-thread max -> per-warp max -> smem[32]
    float tm = rv[0];
    #pragma unroll
    for (int e = 1; e < 8; ++e) tm = fmaxf(tm, rv[e]);
    #pragma unroll
    for (int o = 16; o; o >>= 1) tm = fmaxf(tm, __shfl_xor_sync(0xFFFFFFFFu, tm, o));
    if (lane == 0) wmax[warp] = tm;
    __syncthreads();

    // warp 0: tau = 20th largest of the 32 warp maxima (tau <= x20 provably:
    // if tau > x20 then >=20 warps each contain an element > x20 -> contradiction)
    if (warp == 0) {
        float v = wmax[lane];
        bool used = false;
        float tau = 0.f, rmax = 0.f;
        for (int r = 0; r < TOPN; ++r) {
            float lm = used ? -INFINITY : v;
            float wm = lm;
            #pragma unroll
            for (int o = 16; o; o >>= 1) wm = fmaxf(wm, __shfl_xor_sync(0xFFFFFFFFu, wm, o));
            if (r == 0) rmax = wm;
            tau = wm;
            unsigned bmask = __ballot_sync(0xFFFFFFFFu, lm == wm);
            if (lane == (int)(__ffs(bmask) - 1)) used = true;
        }
        if (lane == 0) { sthr[0] = tau; sthr[1] = rmax; }
    }
    __syncthreads();
    const float tau = sthr[0];

    // collect candidates (val >= tau)
    #pragma unroll
    for (int e = 0; e < 8; ++e) {
        if (rv[e] >= tau) {
            int p = atomicAdd(&ccnt, 1);
            if (p < CANDMAX) {
                cval[p] = rv[e];
                cidx[p] = (e < 4) ? (4 * tid + e) : (4096 + 4 * tid + (e - 4));
            }
        }
    }
    __syncthreads();

    // warp 0: exact top-20 by (val desc, idx asc), sort by idx, softmax p
    if (warp == 0) {
        const int cnt = min(ccnt, CANDMAX);
        for (int r = 0; r < TOPN; ++r) {
            float lm = -INFINITY; int li = 0x7fffffff; int ls = -1;
            for (int i = lane; i < cnt; i += 32) {
                float x = cval[i]; int ix = cidx[i];
                if (x > lm || (x == lm && ix < li)) { lm = x; li = ix; ls = i; }
            }
            #pragma unroll
            for (int o = 16; o; o >>= 1) {
                float ov = __shfl_xor_sync(0xFFFFFFFFu, lm, o);
                int   oi = __shfl_xor_sync(0xFFFFFFFFu, li, o);
                int   os = __shfl_xor_sync(0xFFFFFFFFu, ls, o);
                if (ov > lm || (ov == lm && oi < li)) { lm = ov; li = oi; ls = os; }
            }
            if (lane == 0) { topv_s[r] = lm; topi_s[r] = li; cval[ls] = -INFINITY; }
            __syncwarp();
        }

        // sort the 20 by index (rank = #smaller indices; a permutation)
        float myv = 0.f; int myi = 0x7fffffff;
        if (lane < TOPN) { myv = topv_s[lane]; myi = topi_s[lane]; }
        int rank = 0;
        #pragma unroll
        for (int j = 0; j < TOPN; ++j) rank += (topi_s[j] < myi);
        __syncwarp();
        if (lane < TOPN) { topv_s[rank] = myv; topi_s[rank] = myi; }
        __syncwarp();

        // masked softmax over the 20 (rest underflows to exact 0 in fp32)
        const float rmax = sthr[1];
        float e20 = (lane < TOPN) ? expf(topv_s[lane] - rmax) : 0.f;
        float ps = e20;
        #pragma unroll
        for (int o = 16; o; o >>= 1) ps += __shfl_xor_sync(0xFFFFFFFFu, ps, o);
        const float invp = 1.0f / ps;

        if (lane < TOPN) {
            g_p[k * TOPN + lane]   = e20 * invp;
            int ix = topi_s[lane];
            g_idx[k * TOPN + lane] = ix;
            unsigned w = (unsigned)ix >> 5, mb = 1u << (ix & 31);
            unsigned old = atomicOr(&g_U1[w], mb);
            if (old & mb) atomicOr(&g_U2[w], mb);
        }
        if (lane == 0) g_rowmax[k] = rmax;
    }
}

// ===== kernel 2: fused loss — register-resident M, per-topic rendezvous =====
// 800 blocks x 256 threads; block b = (topic k = b>>3, slice sl = b&7) owns
// 1024 columns (4 per thread): coverage 800*256*4 = 100*8192 exactly.
// Geometry (256 thr, 6 blocks/SM -> 888 slots >= 800) is the SAME the R7
// kernel already ran co-resident with cross-block spins on this machine, so
// the per-topic 8-count rendezvous cannot deadlock. Only the 8 sibling
// blocks of a topic wait on each other (identical work -> tiny skew).
__global__ void __launch_bounds__(256, 6) fused_loss_kernel(
    const float* __restrict__ Wmat, const float* __restrict__ beta,
    const int* __restrict__ epoch, float* __restrict__ out)
{
    __shared__ float  sp[TOPN];
    __shared__ int    si[TOPN];
    __shared__ float  r1[8], r2[8], r3[8];
    __shared__ double d1[8], d2[8];
    __shared__ int    is_last;

    const int b    = blockIdx.x;
    const int k    = b >> 3;
    const int sl   = b & 7;
    const int tid  = threadIdx.x;
    const int warp = tid >> 5;
    const int lane = tid & 31;

    if (tid < TOPN) { sp[tid] = g_p[k * TOPN + tid]; si[tid] = g_idx[k * TOPN + tid]; }
    __syncthreads();

    // ---------------- stage 1: sparse p@W into registers --------------------
    const int v0 = sl * 1024 + tid * 4;
    float ax = 0.f, ay = 0.f, az = 0.f, aw = 0.f;
    #pragma unroll
    for (int j = 0; j < TOPN; ++j) {
        const float pj = sp[j];
        float4 w = __ldg((const float4*)(Wmat + (size_t)si[j] * VDIM + v0));
        ax = fmaf(pj, w.x, ax); ay = fmaf(pj, w.y, ay);
        az = fmaf(pj, w.z, az); aw = fmaf(pj, w.w, aw);
    }

    float mn = fminf(fminf(ax, ay), fminf(az, aw));
    float mx = fmaxf(fmaxf(ax, ay), fmaxf(az, aw));
    #pragma unroll
    for (int o = 16; o; o >>= 1) {
        mn = fminf(mn, __shfl_xor_sync(0xFFFFFFFFu, mn, o));
        mx = fmaxf(mx, __shfl_xor_sync(0xFFFFFFFFu, mx, o));
    }
    if (lane == 0) { r1[warp] = mn; r2[warp] = mx; }
    __syncthreads();
    if (warp == 0) {
        mn = r1[lane & 7]; mx = r2[lane & 7];
        #pragma unroll
        for (int o = 4; o; o >>= 1) {
            mn = fminf(mn, __shfl_xor_sync(0xFFFFFFFFu, mn, o));
            mx = fmaxf(mx, __shfl_xor_sync(0xFFFFFFFFu, mx, o));
        }
        if (lane == 0) {
            // M >= 0 everywhere, so uint ordering == float ordering
            atomicMin(&g_mn[k], __float_as_uint(mn));
            atomicMax(&g_mx[k], __float_as_uint(mx));
            __threadfence();
            atomicAdd(&g_tcnt[k], 1u);
            // per-topic rendezvous: wait only for the 7 sibling blocks
            while (atomicAdd(&g_tcnt[k], 0u) < SLICES) __nanosleep(32);
            __threadfence();
        }
    }
    __syncthreads();

    // ---------------- stage 2: Wc, loss, Md split, rowsum -------------------
    const unsigned word  = (unsigned)v0 >> 5;
    const int      shift = v0 & 31;

    unsigned ow = 0u;
    #pragma unroll
    for (int j = 0; j < TOPN; ++j)
        if (((unsigned)si[j] >> 5) == word) ow |= 1u << (si[j] & 31);

    const float fmn  = __uint_as_float(__ldcg(&g_mn[k]));
    const float fmx  = __uint_as_float(__ldcg(&g_mx[k]));
    const float invr = 1.0f / (fmx - fmn);
    const float rmax = g_rowmax[k];

    float4 bt = __ldg((const float4*)(beta + (size_t)k * VDIM + v0));
    const unsigned u1 = g_U1[word], u2 = g_U2[word];

    float mv[4] = {ax, ay, az, aw};
    float bv[4] = {bt.x, bt.y, bt.z, bt.w};
    float pos = 0.f, neg = 0.f, es = 0.f;
    #pragma unroll
    for (int c = 0; c < 4; ++c) {
        const float wc = 1.0f - (mv[c] - fmn) * invr;
        const float e  = expf(bv[c] - rmax);       // unnormalized softmax numerator
        es += e;
        const float l  = 100.0f * e * e * wc;      // scaled by 1/S^2 at the end
        const unsigned mb = 1u << (shift + c);
        const bool md = (ow & mb) ? (u2 & mb) : (u1 & mb);
        if (md) pos += l; else neg += l;
    }
    #pragma unroll
    for (int o = 16; o; o >>= 1) {
        pos += __shfl_xor_sync(0xFFFFFFFFu, pos, o);
        neg += __shfl_xor_sync(0xFFFFFFFFu, neg, o);
        es  += __shfl_xor_sync(0xFFFFFFFFu, es, o);
    }
    if (lane == 0) { r1[warp] = pos; r2[warp] = neg; r3[warp] = es; }
    __syncthreads();
    if (warp == 0) {
        pos = r1[lane & 7]; neg = r2[lane & 7]; es = r3[lane & 7];
        #pragma unroll
        for (int o = 4; o; o >>= 1) {
            pos += __shfl_xor_sync(0xFFFFFFFFu, pos, o);
            neg += __shfl_xor_sync(0xFFFFFFFFu, neg, o);
            es  += __shfl_xor_sync(0xFFFFFFFFu, es, o);
        }
    }

    if (tid == 0) {
        g_partial[2 * b]     = (double)pos;
        g_partial[2 * b + 1] = (double)neg;
        g_rowsum[b]          = es;
        __threadfence();
        unsigned r = atomicAdd(&g_done, 1u);
        is_last = (r == NB - 1);
    }
    __syncthreads();

    // ---------------- last block: final reduction + replay resets -----------
    if (is_last) {
        __threadfence();
        double P = 0.0, N = 0.0;
        if (tid < KT) {                              // one thread per topic
            double S = 0.0, p = 0.0, n = 0.0;
            #pragma unroll
            for (int s2 = 0; s2 < SLICES; ++s2) {
                S += (double)g_rowsum[SLICES * tid + s2];
                p += g_partial[2 * (SLICES * tid + s2)];
                n += g_partial[2 * (SLICES * tid + s2) + 1];
            }
            const double inv = 1.0 / (S * S);
            P = p * inv; N = n * inv;
        }
        #pragma unroll
        for (int o = 16; o; o >>= 1) {
            P += __shfl_xor_sync(0xFFFFFFFFu, P, o);
            N += __shfl_xor_sync(0xFFFFFFFFu, N, o);
        }
        if (lane == 0) { d1[warp] = P; d2[warp] = N; }
        __syncthreads();
        if (warp == 0) {
            P = d1[lane & 7]; N = d2[lane & 7];
            #pragma unroll
            for (int o = 4; o; o >>= 1) {
                P += __shfl_xor_sync(0xFFFFFFFFu, P, o);
                N += __shfl_xor_sync(0xFFFFFFFFu, N, o);
            }
            if (lane == 0) {
                const int e = *epoch;                 // warmup = 100, delta = 1.0
                const float lam = (e < 100) ? (float)e : 100.0f;
                out[0] = lam * (float)((P * 0.7 + N * 0.3) * 2.0);
                g_done = 0;                           // reset for next replay
            }
        }
        if (tid < NWORDS) { g_U1[tid] = 0u; g_U2[tid] = 0u; }
        if (tid < KT) g_tcnt[tid] = 0u;
    }
}

// ---------------- launch -----------------------------------------------------
extern "C" void kernel_launch(void* const* d_in, const int* in_sizes, int n_in,
                              void* d_out, int out_size) {
    const float* beta  = (const float*)d_in[0];
    const float* Wmat  = (const float*)d_in[1];
    const int*   epoch = (const int*)d_in[2];
    float* out = (float*)d_out;

    topk_kernel<<<KT, 1024>>>(beta);
    fused_loss_kernel<<<NB, 256>>>(Wmat, beta, epoch, out);
}